// round 15
// baseline (speedup 1.0000x reference)
#include <cuda_runtime.h>

#define FULL 0xffffffffu
typedef unsigned long long u64;

static __device__ __forceinline__ u64 pk2(float lo, float hi) {
    u64 r; asm("mov.b64 %0, {%1, %2};" : "=l"(r) : "f"(lo), "f"(hi)); return r;
}
static __device__ __forceinline__ void up2(u64 a, float& lo, float& hi) {
    asm("mov.b64 {%0, %1}, %2;" : "=f"(lo), "=f"(hi) : "l"(a));
}
static __device__ __forceinline__ u64 mul2(u64 a, u64 b) {
    u64 d; asm("mul.rn.f32x2 %0, %1, %2;" : "=l"(d) : "l"(a), "l"(b)); return d;
}
static __device__ __forceinline__ u64 fma2(u64 a, u64 b, u64 c) {
    u64 d; asm("fma.rn.f32x2 %0, %1, %2, %3;" : "=l"(d) : "l"(a), "l"(b), "l"(c)); return d;
}

// One sample per CTA (128 threads). b = (W<<10)|(lane<<5)|r, wire w at bit 11-w.
// Registers are ALWAYS logical: v[r] = psi[(W<<10)|(lane<<5)|r].
//
// Layer exchange layout (per-layer scratch):
//   smem[(rho<<7) | (l<<2) | (c ^ (l>>3))] = psi_pre[ g( (c<<10)|(l<<5)|rho ) ]
// Loads: thread (W,lane) reads float4 at float index (r<<7)|(lane<<2) -> the 4
//   warp-partners of element r (component j holds partner c = j ^ (lane>>3);
//   fixed by reordering combine coefficients). Pure base+immediate, LDS.128,
//   conflict-free (quarter-warps cover banks 0..31 exactly).
// Stores: thread's element r0 belongs at b' = inverse-Gray12(b):
//   c  = (Wb1<<1)|(Wb1^Wb0)            (per-thread const)
//   l' = ig5(lane) ^ parity(W)*31      (per-thread const, = ig7(x)&31)
//   rho= ig5(r0)   ^ parity(W,lane)*31
// Iterating k = ig5(r0) (r0 = gray5(k)): addr = stbase ^ (k<<7), one LOP3 each.
// Store banks ((l'&7)<<2)|(c^(l'>>3)) are bijective over the warp: conflict-free.
__global__ void __launch_bounds__(128, 5) qnn_65481071395397_kernel(
    const float* __restrict__ sb,      // (B, 12)
    const float* __restrict__ params,  // (12,)
    const float* __restrict__ hw,      // (12,)
    const float* __restrict__ hb,      // (1,)
    float* __restrict__ out)           // (B,)
{
    __shared__ __align__(16) float s[4096];
    __shared__ float partial[4];

    const int tid  = threadIdx.x;
    const int lane = tid & 31;
    const int warp = tid >> 5;
    const int sample = blockIdx.x;

    // ---- per-thread addressing constants ----
    const int x = (warp << 5) | lane;
    int y = x; y ^= y >> 1; y ^= y >> 2; y ^= y >> 4;  // ig7(x)
    y &= 127;
    const int lp = y & 31;                              // l' = ig5(lane)^pW*31
    const int cc = (((y >> 6) & 1) << 1) | ((y >> 5) & 1);  // c
    const int stbase = ((y & 1) ? (31 << 7) : 0)        // parity(W,lane)*31 in rho
                     | (lp << 2) | (cc ^ (lp >> 3));
    const int sigma = (lane >> 3) & 3;                  // load component twist
    const float4* const ldb = (const float4*)s + lane;  // float4 idx lane + (r<<5)

    // ---- shared variational angles ----
    float cp[12], sp[12];
#pragma unroll
    for (int w = 0; w < 12; w++)
        __sincosf(0.5f * params[w], &sp[w], &cp[w]);

    // warp-combine coefficients m[W'] = RY0[Wb1][W'b1] * RY1[Wb0][W'b0],
    // reordered so packed coeff j multiplies loaded component j (a_j = m[j^sigma])
    u64 Mv01, Mv23;
    {
        const int b1 = (warp >> 1) & 1, b0 = warp & 1;
        const float r1_0 = b1 ? sp[0] : cp[0];
        const float r1_1 = b1 ? cp[0] : -sp[0];
        const float r0_0 = b0 ? sp[1] : cp[1];
        const float r0_1 = b0 ? cp[1] : -sp[1];
        const float m0 = r1_0 * r0_0, m1 = r1_0 * r0_1;
        const float m2 = r1_1 * r0_0, m3 = r1_1 * r0_1;
        const float t0 = (sigma & 1) ? m1 : m0;
        const float t1 = (sigma & 1) ? m0 : m1;
        const float t2 = (sigma & 1) ? m3 : m2;
        const float t3 = (sigma & 1) ? m2 : m3;
        const float a0 = (sigma & 2) ? t2 : t0;
        const float a1 = (sigma & 2) ? t3 : t1;
        const float a2 = (sigma & 2) ? t0 : t2;
        const float a3 = (sigma & 2) ? t1 : t3;
        Mv01 = pk2(a0, a1);
        Mv23 = pk2(a2, a3);
    }

    // ---- encoding: product state (logical convention, as in passing R4) ----
    float v[32];
    {
        const float* row = sb + (long)sample * 12;
        float ec[12], es[12];
#pragma unroll
        for (int w = 0; w < 12; w++)
            __sincosf(0.5f * row[w], &es[w], &ec[w]);

        float lf = 1.0f;
        lf *= (warp & 2) ? es[0] : ec[0];
        lf *= (warp & 1) ? es[1] : ec[1];
#pragma unroll
        for (int w = 2; w <= 6; w++)
            lf *= ((lane >> (6 - w)) & 1) ? es[w] : ec[w];

        v[0] = lf;
#pragma unroll
        for (int w = 11; w >= 7; w--) {
            const int size = 1 << (11 - w);
#pragma unroll
            for (int i = 0; i < size; i++) {
                v[i + size] = v[i] * es[w];
                v[i]        = v[i] * ec[w];
            }
        }
    }

    // ---- 4 variational layers ----
#pragma unroll 1
    for (int layer = 0; layer < 4; layer++) {
        __syncthreads();
#pragma unroll
        for (int k = 0; k < 32; k++)
            s[stbase ^ (k << 7)] = v[k ^ (k >> 1)];
        __syncthreads();

        // Gray permutation (all 11 CNOTs) + both warp-wire RYs, fused.
#pragma unroll
        for (int r = 0; r < 32; r++) {
            const float4 q = ldb[r << 5];
            u64 acc = mul2(Mv01, pk2(q.x, q.y));
            acc = fma2(Mv23, pk2(q.z, q.w), acc);
            float lo, hi; up2(acc, lo, hi);
            v[r] = lo + hi;
        }

        // RY on reg wires 7..10 (reg bits 4..1), packed f32x2
#pragma unroll
        for (int w = 7; w <= 10; w++) {
            const float c = cp[w], sv = sp[w];
            const int m = 1 << (11 - w);       // 16, 8, 4, 2
            const u64 C2 = pk2(c, c), S2 = pk2(sv, sv), NS2 = pk2(-sv, -sv);
#pragma unroll
            for (int r0 = 0; r0 < 32; r0 += 2) {
                if (r0 & m) continue;
                const u64 a = pk2(v[r0],     v[r0 + 1]);
                const u64 b = pk2(v[r0 + m], v[r0 + m + 1]);
                const u64 n0 = fma2(NS2, b, mul2(C2, a));   // c*a - s*b
                const u64 n1 = fma2(C2,  b, mul2(S2, a));   // s*a + c*b
                up2(n0, v[r0],     v[r0 + 1]);
                up2(n1, v[r0 + m], v[r0 + m + 1]);
            }
        }

        // wire 11 (reg bit 0): scalar within each adjacent pair
        {
            const float c = cp[11], sv = sp[11];
#pragma unroll
            for (int r0 = 0; r0 < 32; r0 += 2) {
                const float a0 = v[r0], a1 = v[r0 + 1];
                v[r0]     = fmaf(-sv, a1, c * a0);
                v[r0 + 1] = fmaf( c,  a1, sv * a0);
            }
        }

        // lane wires 2..6 (lane bit 6-w): shfl.bfly + packed f32x2 (logical regs)
#pragma unroll
        for (int w = 2; w < 7; w++) {
            const float c = cp[w], sv = sp[w];
            const int lm = 1 << (6 - w);
            const float k = (lane & lm) ? sv : -sv;
            const u64 C2 = pk2(c, c), K2 = pk2(k, k);
#pragma unroll
            for (int r0 = 0; r0 < 32; r0 += 2) {
                const float p0 = __shfl_xor_sync(FULL, v[r0],     lm);
                const float p1 = __shfl_xor_sync(FULL, v[r0 + 1], lm);
                const u64 nv = fma2(K2, pk2(p0, p1), mul2(C2, pk2(v[r0], v[r0 + 1])));
                up2(nv, v[r0], v[r0 + 1]);
            }
        }
    }

    // ---- readout: sum_b G(b) * psi_b^2 (logical, as in passing R4) ----
    float gwl = 0.0f;
    gwl += (warp & 2) ? -hw[0] : hw[0];
    gwl += (warp & 1) ? -hw[1] : hw[1];
#pragma unroll
    for (int w = 2; w <= 6; w++)
        gwl += ((lane >> (6 - w)) & 1) ? -hw[w] : hw[w];
    const float h7 = hw[7], h8 = hw[8], h9 = hw[9], h10 = hw[10], h11 = hw[11];

    float acc = 0.0f;
#pragma unroll
    for (int r = 0; r < 32; r++) {
        const float g = gwl
            + ((r & 16) ? -h7  : h7)
            + ((r &  8) ? -h8  : h8)
            + ((r &  4) ? -h9  : h9)
            + ((r &  2) ? -h10 : h10)
            + ((r &  1) ? -h11 : h11);
        acc = fmaf(v[r] * g, v[r], acc);
    }

#pragma unroll
    for (int off = 16; off > 0; off >>= 1)
        acc += __shfl_xor_sync(FULL, acc, off);

    if (lane == 0) partial[warp] = acc;
    __syncthreads();
    if (tid == 0)
        out[sample] = (partial[0] + partial[1]) + (partial[2] + partial[3]) + hb[0];
}

extern "C" void kernel_launch(void* const* d_in, const int* in_sizes, int n_in,
                              void* d_out, int out_size) {
    const float* sb     = (const float*)d_in[0];
    const float* params = (const float*)d_in[1];
    const float* hw     = (const float*)d_in[2];
    const float* hb     = (const float*)d_in[3];
    float*       out    = (float*)d_out;

    const int B = in_sizes[0] / 12;   // 8192
    qnn_65481071395397_kernel<<<B, 128>>>(sb, params, hw, hb, out);
}

// round 16
// speedup vs baseline: 1.0035x; 1.0035x over previous
#include <cuda_runtime.h>

#define FULL 0xffffffffu
typedef unsigned long long u64;

static __device__ __forceinline__ u64 pk2(float lo, float hi) {
    u64 r; asm("mov.b64 %0, {%1, %2};" : "=l"(r) : "f"(lo), "f"(hi)); return r;
}
static __device__ __forceinline__ void up2(u64 a, float& lo, float& hi) {
    asm("mov.b64 {%0, %1}, %2;" : "=f"(lo), "=f"(hi) : "l"(a));
}
static __device__ __forceinline__ u64 mul2(u64 a, u64 b) {
    u64 d; asm("mul.rn.f32x2 %0, %1, %2;" : "=l"(d) : "l"(a), "l"(b)); return d;
}
static __device__ __forceinline__ u64 fma2(u64 a, u64 b, u64 c) {
    u64 d; asm("fma.rn.f32x2 %0, %1, %2, %3;" : "=l"(d) : "l"(a), "l"(b), "l"(c)); return d;
}

// One sample per CTA (128 threads). b = (W<<10)|(lane<<5)|r, wire w at bit 11-w.
// Registers are ALWAYS logical: v[r] = psi[(W<<10)|(lane<<5)|r].
//
// Layer exchange layout (per-layer scratch):
//   smem[(rho<<7) | (l<<2) | (c ^ (l>>3))] = psi_pre[ g( (c<<10)|(l<<5)|rho ) ]
// Loads: thread (W,lane) reads float4 at float index (r<<7)|(lane<<2) -> the 4
//   warp-partners of element r (component j holds partner c = j ^ (lane>>3);
//   fixed by reordering combine coefficients). Pure base+immediate, LDS.128,
//   conflict-free (quarter-warps cover banks 0..31 exactly).
// Stores: thread's element r0 belongs at b' = inverse-Gray12(b):
//   c  = (Wb1<<1)|(Wb1^Wb0)            (per-thread const)
//   l' = ig5(lane) ^ parity(W)*31      (per-thread const, = ig7(x)&31)
//   rho= ig5(r0)   ^ parity(W,lane)*31
// Iterating k = ig5(r0) (r0 = gray5(k)): addr = stbase ^ (k<<7), one LOP3 each.
// Store banks ((l'&7)<<2)|(c^(l'>>3)) are bijective over the warp: conflict-free.
__global__ void __launch_bounds__(128, 5) qnn_65481071395397_kernel(
    const float* __restrict__ sb,      // (B, 12)
    const float* __restrict__ params,  // (12,)
    const float* __restrict__ hw,      // (12,)
    const float* __restrict__ hb,      // (1,)
    float* __restrict__ out)           // (B,)
{
    __shared__ __align__(16) float s[4096];
    __shared__ float partial[4];

    const int tid  = threadIdx.x;
    const int lane = tid & 31;
    const int warp = tid >> 5;
    const int sample = blockIdx.x;

    // ---- per-thread addressing constants ----
    const int x = (warp << 5) | lane;
    int y = x; y ^= y >> 1; y ^= y >> 2; y ^= y >> 4;  // ig7(x)
    y &= 127;
    const int lp = y & 31;                              // l' = ig5(lane)^pW*31
    const int cc = (((y >> 6) & 1) << 1) | ((y >> 5) & 1);  // c
    const int stbase = ((y & 1) ? (31 << 7) : 0)        // parity(W,lane)*31 in rho
                     | (lp << 2) | (cc ^ (lp >> 3));
    const int sigma = (lane >> 3) & 3;                  // load component twist
    const float4* const ldb = (const float4*)s + lane;  // float4 idx lane + (r<<5)

    // ---- shared variational angles ----
    float cp[12], sp[12];
#pragma unroll
    for (int w = 0; w < 12; w++)
        __sincosf(0.5f * params[w], &sp[w], &cp[w]);

    // warp-combine coefficients m[W'] = RY0[Wb1][W'b1] * RY1[Wb0][W'b0],
    // reordered so packed coeff j multiplies loaded component j (a_j = m[j^sigma])
    u64 Mv01, Mv23;
    {
        const int b1 = (warp >> 1) & 1, b0 = warp & 1;
        const float r1_0 = b1 ? sp[0] : cp[0];
        const float r1_1 = b1 ? cp[0] : -sp[0];
        const float r0_0 = b0 ? sp[1] : cp[1];
        const float r0_1 = b0 ? cp[1] : -sp[1];
        const float m0 = r1_0 * r0_0, m1 = r1_0 * r0_1;
        const float m2 = r1_1 * r0_0, m3 = r1_1 * r0_1;
        const float t0 = (sigma & 1) ? m1 : m0;
        const float t1 = (sigma & 1) ? m0 : m1;
        const float t2 = (sigma & 1) ? m3 : m2;
        const float t3 = (sigma & 1) ? m2 : m3;
        const float a0 = (sigma & 2) ? t2 : t0;
        const float a1 = (sigma & 2) ? t3 : t1;
        const float a2 = (sigma & 2) ? t0 : t2;
        const float a3 = (sigma & 2) ? t1 : t3;
        Mv01 = pk2(a0, a1);
        Mv23 = pk2(a2, a3);
    }

    // ---- encoding: product state (logical convention, as in passing R4) ----
    float v[32];
    {
        const float* row = sb + (long)sample * 12;
        float ec[12], es[12];
#pragma unroll
        for (int w = 0; w < 12; w++)
            __sincosf(0.5f * row[w], &es[w], &ec[w]);

        float lf = 1.0f;
        lf *= (warp & 2) ? es[0] : ec[0];
        lf *= (warp & 1) ? es[1] : ec[1];
#pragma unroll
        for (int w = 2; w <= 6; w++)
            lf *= ((lane >> (6 - w)) & 1) ? es[w] : ec[w];

        v[0] = lf;
#pragma unroll
        for (int w = 11; w >= 7; w--) {
            const int size = 1 << (11 - w);
#pragma unroll
            for (int i = 0; i < size; i++) {
                v[i + size] = v[i] * es[w];
                v[i]        = v[i] * ec[w];
            }
        }
    }

    // ---- 4 variational layers ----
#pragma unroll 1
    for (int layer = 0; layer < 4; layer++) {
        __syncthreads();
#pragma unroll
        for (int k = 0; k < 32; k++)
            s[stbase ^ (k << 7)] = v[k ^ (k >> 1)];
        __syncthreads();

        // Gray permutation (all 11 CNOTs) + both warp-wire RYs, fused.
#pragma unroll
        for (int r = 0; r < 32; r++) {
            const float4 q = ldb[r << 5];
            u64 acc = mul2(Mv01, pk2(q.x, q.y));
            acc = fma2(Mv23, pk2(q.z, q.w), acc);
            float lo, hi; up2(acc, lo, hi);
            v[r] = lo + hi;
        }

        // RY on reg wires 7..10 (reg bits 4..1), packed f32x2
#pragma unroll
        for (int w = 7; w <= 10; w++) {
            const float c = cp[w], sv = sp[w];
            const int m = 1 << (11 - w);       // 16, 8, 4, 2
            const u64 C2 = pk2(c, c), S2 = pk2(sv, sv), NS2 = pk2(-sv, -sv);
#pragma unroll
            for (int r0 = 0; r0 < 32; r0 += 2) {
                if (r0 & m) continue;
                const u64 a = pk2(v[r0],     v[r0 + 1]);
                const u64 b = pk2(v[r0 + m], v[r0 + m + 1]);
                const u64 n0 = fma2(NS2, b, mul2(C2, a));   // c*a - s*b
                const u64 n1 = fma2(C2,  b, mul2(S2, a));   // s*a + c*b
                up2(n0, v[r0],     v[r0 + 1]);
                up2(n1, v[r0 + m], v[r0 + m + 1]);
            }
        }

        // wire 11 (reg bit 0): scalar within each adjacent pair
        {
            const float c = cp[11], sv = sp[11];
#pragma unroll
            for (int r0 = 0; r0 < 32; r0 += 2) {
                const float a0 = v[r0], a1 = v[r0 + 1];
                v[r0]     = fmaf(-sv, a1, c * a0);
                v[r0 + 1] = fmaf( c,  a1, sv * a0);
            }
        }

        // lane wires 2..6 (lane bit 6-w): shfl.bfly + packed f32x2 (logical regs)
#pragma unroll
        for (int w = 2; w < 7; w++) {
            const float c = cp[w], sv = sp[w];
            const int lm = 1 << (6 - w);
            const float k = (lane & lm) ? sv : -sv;
            const u64 C2 = pk2(c, c), K2 = pk2(k, k);
#pragma unroll
            for (int r0 = 0; r0 < 32; r0 += 2) {
                const float p0 = __shfl_xor_sync(FULL, v[r0],     lm);
                const float p1 = __shfl_xor_sync(FULL, v[r0 + 1], lm);
                const u64 nv = fma2(K2, pk2(p0, p1), mul2(C2, pk2(v[r0], v[r0 + 1])));
                up2(nv, v[r0], v[r0 + 1]);
            }
        }
    }

    // ---- readout: sum_b G(b) * psi_b^2 (logical, as in passing R4) ----
    float gwl = 0.0f;
    gwl += (warp & 2) ? -hw[0] : hw[0];
    gwl += (warp & 1) ? -hw[1] : hw[1];
#pragma unroll
    for (int w = 2; w <= 6; w++)
        gwl += ((lane >> (6 - w)) & 1) ? -hw[w] : hw[w];
    const float h7 = hw[7], h8 = hw[8], h9 = hw[9], h10 = hw[10], h11 = hw[11];

    float acc = 0.0f;
#pragma unroll
    for (int r = 0; r < 32; r++) {
        const float g = gwl
            + ((r & 16) ? -h7  : h7)
            + ((r &  8) ? -h8  : h8)
            + ((r &  4) ? -h9  : h9)
            + ((r &  2) ? -h10 : h10)
            + ((r &  1) ? -h11 : h11);
        acc = fmaf(v[r] * g, v[r], acc);
    }

#pragma unroll
    for (int off = 16; off > 0; off >>= 1)
        acc += __shfl_xor_sync(FULL, acc, off);

    if (lane == 0) partial[warp] = acc;
    __syncthreads();
    if (tid == 0)
        out[sample] = (partial[0] + partial[1]) + (partial[2] + partial[3]) + hb[0];
}

extern "C" void kernel_launch(void* const* d_in, const int* in_sizes, int n_in,
                              void* d_out, int out_size) {
    const float* sb     = (const float*)d_in[0];
    const float* params = (const float*)d_in[1];
    const float* hw     = (const float*)d_in[2];
    const float* hb     = (const float*)d_in[3];
    float*       out    = (float*)d_out;

    const int B = in_sizes[0] / 12;   // 8192
    qnn_65481071395397_kernel<<<B, 128>>>(sb, params, hw, hb, out);
}